// round 1
// baseline (speedup 1.0000x reference)
#include <cuda_runtime.h>

#define VSZ   50257
#define Dk    50
#define TT    1024
#define BSZ   1024
#define NU1   32
#define NU2   64
#define NG1   96
#define NG2   192
#define NGLU  128
#define BB    8
#define NT    192

// Precomputed emb @ kx1 + b1[0] table: [V, 96] fp32, 19.3MB (L2-resident)
__device__ float g_proj1[VSZ * NG1];

typedef unsigned long long u64;

__device__ __forceinline__ u64 pk2(float a, float b) {
    u64 r; asm("mov.b64 %0, {%1, %2};" : "=l"(r) : "f"(a), "f"(b)); return r;
}
__device__ __forceinline__ void upk2(u64 v, float& a, float& b) {
    asm("mov.b64 {%0, %1}, %2;" : "=f"(a), "=f"(b) : "l"(v));
}
// packed dual-fp32 FMA (sm_100+): d = a*b + c elementwise
__device__ __forceinline__ u64 ffma2(u64 a, u64 b, u64 c) {
    u64 d; asm("fma.rn.f32x2 %0, %1, %2, %3;" : "=l"(d) : "l"(a), "l"(b), "l"(c)); return d;
}
__device__ __forceinline__ float sgm(float x) { return 1.0f / (1.0f + __expf(-x)); }
__device__ __forceinline__ float tnh(float x) { return 2.0f * sgm(2.0f * x) - 1.0f; }

// ---------------------------------------------------------------------------
// Precompute g_proj1[v][j] = sum_d emb[v][d]*kx1[d][j] + b1[0][j]
// ---------------------------------------------------------------------------
__global__ void proj_kernel(const float* __restrict__ emb,
                            const float* __restrict__ kx1,
                            const float* __restrict__ b1) {
    __shared__ float kxs[Dk * NG1];     // 19.2 KB
    __shared__ float embs[16 * Dk];
    int tid = threadIdx.x;              // 256 threads
    for (int i = tid; i < Dk * NG1; i += 256) kxs[i] = kx1[i];
    int vbase = blockIdx.x * 16;
    for (int i = tid; i < 16 * Dk; i += 256) {
        int r = i / Dk, d = i - r * Dk;
        int v = vbase + r;
        embs[i] = (v < VSZ) ? emb[v * Dk + d] : 0.0f;
    }
    __syncthreads();
    for (int i = tid; i < 16 * NG1; i += 256) {
        int r = i / NG1, j = i - r * NG1;
        int v = vbase + r;
        if (v >= VSZ) continue;
        float acc = b1[j];
        #pragma unroll
        for (int d = 0; d < Dk; d++)
            acc = fmaf(embs[r * Dk + d], kxs[d * NG1 + j], acc);
        g_proj1[v * NG1 + j] = acc;
    }
}

// ---------------------------------------------------------------------------
// Fused persistent GRU stack: each CTA owns 8 batch rows for all 1024 steps.
// ---------------------------------------------------------------------------
__global__ void __launch_bounds__(NT, 1) rnn_kernel(
    const int*   __restrict__ tokens,  // [B,T]
    const float* __restrict__ kh1,     // [32,96]
    const float* __restrict__ b1,      // [2,96]
    const float* __restrict__ kx2,     // [32,192]
    const float* __restrict__ kh2,     // [64,192]
    const float* __restrict__ b2,      // [2,192]
    const float* __restrict__ wg,      // [64,256]
    const float* __restrict__ bg,      // [256]
    const float* __restrict__ wd,      // [128]
    const float* __restrict__ bd,      // [1]
    float*       __restrict__ out)     // [B]
{
    // States as f32x2 batch-pairs, u-major (broadcast LDS.128 in GEMM phases)
    __shared__ __align__(16) u64   h1p[NU1][4];      // pair p = batches (2p,2p+1)
    __shared__ __align__(16) u64   h2p[NU2][4];
    __shared__ __align__(16) float hm1s[BB][NG1];
    __shared__ __align__(16) float xg1s[2][BB][NG1]; // gathered proj, double buffered
    __shared__ __align__(16) float xg2s[BB][NG2];
    __shared__ __align__(16) float hm2s[BB][NG2];
    __shared__ int   tokbuf[BB][32];
    __shared__ float ags[BB][256];
    __shared__ float gws[BB][NGLU];

    const int tid = threadIdx.x;
    const int b0  = blockIdx.x * BB;

    // -------- weights into registers (step-invariant, reused 1024x) --------
    const int j1   = tid % NG1;     // kh1 column
    const int half = tid / NG1;     // batch halves {0..3} vs {4..7}
    float wkh1[NU1];
    #pragma unroll
    for (int u = 0; u < NU1; u++) wkh1[u] = kh1[u * NG1 + j1];
    const float bh1 = b1[NG1 + j1];

    const int j2 = tid;             // 0..191
    float wkx2[NU1];
    #pragma unroll
    for (int u = 0; u < NU1; u++) wkx2[u] = kx2[u * NG2 + j2];
    float wkh2[NU2];
    #pragma unroll
    for (int u = 0; u < NU2; u++) wkh2[u] = kh2[u * NG2 + j2];
    const float bx2 = b2[j2];
    const float bh2 = b2[NG2 + j2];

    // -------- init state, token chunk [0,32), gather for t=0 --------
    if (tid < NU1 * 4) ((u64*)h1p)[tid] = 0ull;
    for (int i = tid; i < NU2 * 4; i += NT) ((u64*)h2p)[i] = 0ull;
    for (int i = tid; i < BB * 32; i += NT) {
        int b = i >> 5, o = i & 31;
        tokbuf[b][o] = tokens[(b0 + b) * TT + o];
    }
    __syncthreads();
    #pragma unroll
    for (int k = 0; k < 4; k++) {
        int idx = tid + NT * k;
        int b = idx / NG1, jj = idx - b * NG1;
        xg1s[0][b][jj] = __ldg(&g_proj1[tokbuf[b][0] * NG1 + jj]);
    }
    __syncthreads();

    float gv[4];  // prefetched gathers, carried P2 -> P4 across barriers

    #pragma unroll 1
    for (int t = 0; t < TT; t++) {
        const int cb = t & 1, nb = cb ^ 1;
        const int tn = t + 1;

        // ================= P1: hm1 = h1 @ kh1 + b1[1] =================
        {
            u64 acc0 = pk2(bh1, bh1), acc1 = acc0;
            #pragma unroll
            for (int u = 0; u < NU1; u++) {
                ulonglong2 h = *reinterpret_cast<const ulonglong2*>(&h1p[u][2 * half]);
                u64 w = pk2(wkh1[u], wkh1[u]);
                acc0 = ffma2(w, h.x, acc0);
                acc1 = ffma2(w, h.y, acc1);
            }
            float f0, f1, f2, f3;
            upk2(acc0, f0, f1); upk2(acc1, f2, f3);
            int bb = 4 * half;
            hm1s[bb + 0][j1] = f0; hm1s[bb + 1][j1] = f1;
            hm1s[bb + 2][j1] = f2; hm1s[bb + 3][j1] = f3;
        }
        // token chunk reload (every 32 steps)
        if (tn < TT && (tn & 31) == 0) {
            for (int i = tid; i < BB * 32; i += NT) {
                int b = i >> 5, o = i & 31;
                tokbuf[b][o] = tokens[(b0 + b) * TT + tn + o];
            }
        }
        __syncthreads();  // sync1

        // ===== P2: issue next-step gathers (all) + GRU1 gates (tid<128) =====
        if (tn < TT) {
            #pragma unroll
            for (int k = 0; k < 4; k++) {
                int idx = tid + NT * k;
                int b = idx / NG1, jj = idx - b * NG1;
                gv[k] = __ldg(&g_proj1[tokbuf[b][tn & 31] * NG1 + jj]);
            }
        }
        if (tid < 128) {
            int i = tid & 31, bp = tid >> 5, ba = 2 * bp;
            float h0o, h1o; upk2(h1p[i][bp], h0o, h1o);
            float z0 = sgm(xg1s[cb][ba    ][i]        + hm1s[ba    ][i]);
            float z1 = sgm(xg1s[cb][ba + 1][i]        + hm1s[ba + 1][i]);
            float r0 = sgm(xg1s[cb][ba    ][NU1 + i]  + hm1s[ba    ][NU1 + i]);
            float r1 = sgm(xg1s[cb][ba + 1][NU1 + i]  + hm1s[ba + 1][NU1 + i]);
            float c0 = tnh(xg1s[cb][ba    ][2*NU1 + i] + r0 * hm1s[ba    ][2*NU1 + i]);
            float c1 = tnh(xg1s[cb][ba + 1][2*NU1 + i] + r1 * hm1s[ba + 1][2*NU1 + i]);
            float n0 = z0 * h0o + (1.0f - z0) * c0;
            float n1 = z1 * h1o + (1.0f - z1) * c1;
            h1p[i][bp] = pk2(n0, n1);
        }
        __syncthreads();  // sync2

        // ===== P3: xg2 = h1new @ kx2 + b2[0]; hm2 = h2 @ kh2 + b2[1] =====
        {
            u64 ax[4], ah[4];
            u64 bxp = pk2(bx2, bx2), bhp = pk2(bh2, bh2);
            #pragma unroll
            for (int p = 0; p < 4; p++) { ax[p] = bxp; ah[p] = bhp; }
            #pragma unroll
            for (int u = 0; u < NU1; u++) {
                ulonglong2 ha = *reinterpret_cast<const ulonglong2*>(&h1p[u][0]);
                ulonglong2 hb = *reinterpret_cast<const ulonglong2*>(&h1p[u][2]);
                u64 w = pk2(wkx2[u], wkx2[u]);
                ax[0] = ffma2(w, ha.x, ax[0]); ax[1] = ffma2(w, ha.y, ax[1]);
                ax[2] = ffma2(w, hb.x, ax[2]); ax[3] = ffma2(w, hb.y, ax[3]);
            }
            #pragma unroll
            for (int u = 0; u < NU2; u++) {
                ulonglong2 ha = *reinterpret_cast<const ulonglong2*>(&h2p[u][0]);
                ulonglong2 hb = *reinterpret_cast<const ulonglong2*>(&h2p[u][2]);
                u64 w = pk2(wkh2[u], wkh2[u]);
                ah[0] = ffma2(w, ha.x, ah[0]); ah[1] = ffma2(w, ha.y, ah[1]);
                ah[2] = ffma2(w, hb.x, ah[2]); ah[3] = ffma2(w, hb.y, ah[3]);
            }
            float f[8];
            #pragma unroll
            for (int p = 0; p < 4; p++) upk2(ax[p], f[2*p], f[2*p+1]);
            #pragma unroll
            for (int b = 0; b < 8; b++) xg2s[b][j2] = f[b];
            #pragma unroll
            for (int p = 0; p < 4; p++) upk2(ah[p], f[2*p], f[2*p+1]);
            #pragma unroll
            for (int b = 0; b < 8; b++) hm2s[b][j2] = f[b];
        }
        __syncthreads();  // sync3

        // ===== P4: store gathers + GRU2 gates (256 pair-tasks) =====
        if (tn < TT) {
            #pragma unroll
            for (int k = 0; k < 4; k++) {
                int idx = tid + NT * k;
                int b = idx / NG1, jj = idx - b * NG1;
                xg1s[nb][b][jj] = gv[k];
            }
        }
        #pragma unroll
        for (int rep = 0; rep < 2; rep++) {
            int task = tid + rep * NT;
            if (task < 256) {
                int i = task & 63, bp = task >> 6, ba = 2 * bp;
                float h0o, h1o; upk2(h2p[i][bp], h0o, h1o);
                float z0 = sgm(xg2s[ba    ][i]         + hm2s[ba    ][i]);
                float z1 = sgm(xg2s[ba + 1][i]         + hm2s[ba + 1][i]);
                float r0 = sgm(xg2s[ba    ][NU2 + i]   + hm2s[ba    ][NU2 + i]);
                float r1 = sgm(xg2s[ba + 1][NU2 + i]   + hm2s[ba + 1][NU2 + i]);
                float c0 = tnh(xg2s[ba    ][2*NU2 + i] + r0 * hm2s[ba    ][2*NU2 + i]);
                float c1 = tnh(xg2s[ba + 1][2*NU2 + i] + r1 * hm2s[ba + 1][2*NU2 + i]);
                float n0 = z0 * h0o + (1.0f - z0) * c0;
                float n1 = z1 * h1o + (1.0f - z1) * c1;
                h2p[i][bp] = pk2(n0, n1);
            }
        }
        __syncthreads();  // sync4
    }

    // ================= Epilogue: GLU + dense + sigmoid =================
    // E1: a[b][c] = h2[b] @ wg[:,c] + bg[c]
    for (int c = tid; c < 256; c += NT) {
        u64 acc[4];
        u64 bgp = pk2(bg[c], bg[c]);
        #pragma unroll
        for (int p = 0; p < 4; p++) acc[p] = bgp;
        #pragma unroll
        for (int u = 0; u < NU2; u++) {
            ulonglong2 ha = *reinterpret_cast<const ulonglong2*>(&h2p[u][0]);
            ulonglong2 hb = *reinterpret_cast<const ulonglong2*>(&h2p[u][2]);
            float wv = __ldg(&wg[u * 256 + c]);
            u64 w = pk2(wv, wv);
            acc[0] = ffma2(w, ha.x, acc[0]); acc[1] = ffma2(w, ha.y, acc[1]);
            acc[2] = ffma2(w, hb.x, acc[2]); acc[3] = ffma2(w, hb.y, acc[3]);
        }
        float f[8];
        #pragma unroll
        for (int p = 0; p < 4; p++) upk2(acc[p], f[2*p], f[2*p+1]);
        #pragma unroll
        for (int b = 0; b < 8; b++) ags[b][c] = f[b];
    }
    __syncthreads();
    // E2: gws[b][k] = (a[b][k] * sigmoid(a[b][128+k])) * wd[k]
    for (int task = tid; task < NGLU * BB; task += NT) {
        int b = task >> 7, k = task & 127;
        float g = ags[b][k] * sgm(ags[b][NGLU + k]);
        gws[b][k] = g * __ldg(&wd[k]);
    }
    __syncthreads();
    // E3: deterministic serial reduce + final sigmoid
    if (tid < BB) {
        float s = bd[0];
        #pragma unroll
        for (int k = 0; k < NGLU; k++) s += gws[tid][k];
        out[b0 + tid] = sgm(s);
    }
}

// ---------------------------------------------------------------------------
extern "C" void kernel_launch(void* const* d_in, const int* in_sizes, int n_in,
                              void* d_out, int out_size) {
    (void)in_sizes; (void)n_in; (void)out_size;
    const int*   tokens = (const int*)  d_in[0];
    const float* emb    = (const float*)d_in[1];
    const float* kx1    = (const float*)d_in[2];
    const float* kh1    = (const float*)d_in[3];
    const float* b1     = (const float*)d_in[4];
    const float* kx2    = (const float*)d_in[5];
    const float* kh2    = (const float*)d_in[6];
    const float* b2     = (const float*)d_in[7];
    const float* wg     = (const float*)d_in[8];
    const float* bg     = (const float*)d_in[9];
    const float* wd     = (const float*)d_in[10];
    const float* bd     = (const float*)d_in[11];

    proj_kernel<<<(VSZ + 15) / 16, 256>>>(emb, kx1, b1);
    rnn_kernel<<<BSZ / BB, NT>>>(tokens, kh1, b1, kx2, kh2, b2,
                                 wg, bg, wd, bd, (float*)d_out);
}